// round 7
// baseline (speedup 1.0000x reference)
#include <cuda_runtime.h>
#include <cuda_fp16.h>
#include <cstdint>

// ============================================================================
// Problem constants
// ============================================================================
#define M_TOTAL 8192   // B*S = 4*2048
#define DIN     2048
#define DOUT    2048
#define QDIV    358.4f // 448 * 0.8

// GEMM tiling (f16 carrier): 64x128 CTA tile, BK=64, 4 stages, 256 threads,
// 2 CTAs per SM. grid = 2048 CTAs -> 6.9 waves of 296 (tiny tail).
#define BM 64
#define BN 128
#define BK 64
#define STAGES 4
#define NIT (DIN / BK)   // 32

// ============================================================================
// Device-global scratch (allocation-free requirement)
// ============================================================================
__device__ unsigned g_amax_x_bits;
__device__ unsigned g_amax_w_bits;
// fp8-rounded values stored as f16 (exact: e4m3 subset of f16)
__device__ __align__(128) __half g_qx[(size_t)M_TOTAL * DIN];   // 32 MB
__device__ __align__(128) __half g_qw[(size_t)DOUT * DIN];      //  8 MB

// ============================================================================
// Helpers
// ============================================================================
__device__ __forceinline__ uint32_t smem_to_u32(const void* p) {
    uint32_t a;
    asm("{ .reg .u64 t; cvta.to.shared.u64 t, %1; cvt.u32.u64 %0, t; }"
        : "=r"(a) : "l"(p));
    return a;
}

// fp32x2 -> packed e4m3x2 (RN, satfinite). low byte = lo, high byte = hi.
__device__ __forceinline__ uint16_t cvt_e4m3x2(float hi, float lo) {
    uint16_t r;
    asm("cvt.rn.satfinite.e4m3x2.f32 %0, %1, %2;" : "=h"(r) : "f"(hi), "f"(lo));
    return r;
}

// packed e4m3x2 -> f16x2 (exact)
__device__ __forceinline__ uint32_t cvt_f16x2_from_e4m3x2(uint16_t e) {
    uint32_t r;
    asm("cvt.rn.f16x2.e4m3x2 %0, %1;" : "=r"(r) : "h"(e));
    return r;
}

#define CP_ASYNC_16(dst, src) \
    asm volatile("cp.async.cg.shared.global [%0], [%1], 16;" \
                 :: "r"(dst), "l"(src))
#define CP_ASYNC_COMMIT() asm volatile("cp.async.commit_group;")
#define CP_ASYNC_WAIT_3() asm volatile("cp.async.wait_group 3;")

#define LDSM_X4(r, addr) \
    asm volatile("ldmatrix.sync.aligned.m8n8.x4.shared.b16 {%0,%1,%2,%3}, [%4];" \
        : "=r"((r)[0]), "=r"((r)[1]), "=r"((r)[2]), "=r"((r)[3]) : "r"(addr))

__device__ __forceinline__ void mma16816(float* d, const uint32_t* a,
                                         const uint32_t* b) {
    asm volatile(
        "mma.sync.aligned.m16n8k16.row.col.f32.f16.f16.f32 "
        "{%0,%1,%2,%3}, {%4,%5,%6,%7}, {%8,%9}, {%0,%1,%2,%3};"
        : "+f"(d[0]), "+f"(d[1]), "+f"(d[2]), "+f"(d[3])
        : "r"(a[0]), "r"(a[1]), "r"(a[2]), "r"(a[3]), "r"(b[0]), "r"(b[1]));
}

// SW128 swizzle for 128-byte rows (byte offsets)
__device__ __forceinline__ uint32_t swz(uint32_t off) {
    return off ^ ((off >> 3) & 0x70);
}

// div via reciprocal + one FMA residual refinement (== IEEE div for all but
// ~2^-40 of inputs; 3-mantissa-bit e4m3 RNE absorbs the rest)
__device__ __forceinline__ float div_cr(float x, float s, float inv) {
    float y = x * inv;
    float e = fmaf(-s, y, x);
    return fmaf(e, inv, y);
}

// ============================================================================
// Kernel 0: zero the amax scratch
// ============================================================================
__global__ void init_kernel() {
    g_amax_x_bits = 0u;
    g_amax_w_bits = 0u;
}

// ============================================================================
// Kernel 1: fused amax over x (blocks [0,1024)) and w (blocks [1024,1536))
// atomicMax on positive-float bits is order-exact.
// ============================================================================
__global__ void amax_kernel(const float4* __restrict__ x,
                            const float4* __restrict__ w) {
    const bool is_w = blockIdx.x >= 1024;
    const float4* p = is_w ? w : x;
    const int n4 = is_w ? (DOUT * DIN / 4) : (M_TOTAL * DIN / 4);
    const int nblk = is_w ? 512 : 1024;
    const int b0 = is_w ? 1024 : 0;
    float m = 0.0f;
    for (int i = (blockIdx.x - b0) * blockDim.x + threadIdx.x; i < n4;
         i += nblk * blockDim.x) {
        float4 v = p[i];
        m = fmaxf(m, fmaxf(fmaxf(fabsf(v.x), fabsf(v.y)),
                           fmaxf(fabsf(v.z), fabsf(v.w))));
    }
    #pragma unroll
    for (int o = 16; o; o >>= 1)
        m = fmaxf(m, __shfl_xor_sync(0xFFFFFFFFu, m, o));
    if ((threadIdx.x & 31) == 0)
        atomicMax(is_w ? &g_amax_w_bits : &g_amax_x_bits, __float_as_uint(m));
}

// ============================================================================
// Kernel 2: fused quantize x (blocks [0,4096)) and w (blocks [4096,5120)).
// Scales computed inline from the amax globals (deterministic recompute).
// Output: e4m3-rounded value stored exactly as f16.
// ============================================================================
__global__ void quant_kernel(const float4* __restrict__ x,
                             const float4* __restrict__ w) {
    const float ax = __uint_as_float(g_amax_x_bits);
    const float aw = __uint_as_float(g_amax_w_bits);
    const bool is_w = blockIdx.x >= 4096;
    const float s   = is_w ? (fmaxf(ax, aw) / QDIV) : (ax / QDIV);
    const float inv = 1.0f / s;
    const float4* p = is_w ? w : x;
    uint2* q = (uint2*)(is_w ? (void*)g_qw : (void*)g_qx);
    const int n4 = is_w ? (DOUT * DIN / 4) : (M_TOTAL * DIN / 4);
    const int nblk = is_w ? 1024 : 4096;
    const int b0 = is_w ? 4096 : 0;
    for (int i = (blockIdx.x - b0) * blockDim.x + threadIdx.x; i < n4;
         i += nblk * blockDim.x) {
        float4 v = p[i];
        float y0 = div_cr(v.x, s, inv);
        float y1 = div_cr(v.y, s, inv);
        float y2 = div_cr(v.z, s, inv);
        float y3 = div_cr(v.w, s, inv);
        uint2 o;
        o.x = cvt_f16x2_from_e4m3x2(cvt_e4m3x2(y1, y0));
        o.y = cvt_f16x2_from_e4m3x2(cvt_e4m3x2(y3, y2));
        q[i] = o;
    }
}

// ============================================================================
// Kernel 3: f16 HMMA GEMM. out[m,n] = (sum_k qx[m,k]*qw[n,k])*osc + bias[n]
// 64x128x64 CTA tile, 4-stage cp.async (wait_group 3), SW128 swizzle,
// 2 CTAs/SM, 8 warps 2(M)x4(N), warp tile 32x32, m16n8k16,
// intra-stage fragment double buffering.
// ============================================================================
#define A_STAGE_BYTES 8192                // 64 rows x 128B
#define B_STAGE_BYTES 16384               // 128 rows x 128B
#define STAGE_BYTES (A_STAGE_BYTES + B_STAGE_BYTES)   // 24576
#define GEMM_SMEM_BYTES (STAGES * STAGE_BYTES)        // 98304

__global__ __launch_bounds__(256, 2) void gemm_kernel(
    float* __restrict__ out, const float* __restrict__ bias)
{
    extern __shared__ char smem[];
    const uint32_t sb = smem_to_u32(smem);
    const int tid  = threadIdx.x;
    const int lane = tid & 31;
    const int warp = tid >> 5;
    const int wm = warp >> 2;       // 0..1
    const int wn = warp & 3;        // 0..3
    const int nt = blockIdx.x;      // 0..15
    const int mt = blockIdx.y;      // 0..127

    const __half* gA = g_qx + (size_t)mt * BM * DIN;
    const __half* gB = g_qw + (size_t)nt * BN * DIN;

    // ---- per-thread cp.async chunk maps: A 512 chunks (2/thr), B 1024 (4/thr)
    uint32_t dstA[2], dstB[4];
    const char* srcA[2];
    const char* srcB[4];
    #pragma unroll
    for (int q = 0; q < 2; ++q) {
        int ch  = tid + q * 256;
        int row = ch >> 3;
        int cb  = (ch & 7) * 16;
        dstA[q] = swz((uint32_t)(row * 128 + cb));
        srcA[q] = (const char*)(gA + (size_t)row * DIN) + cb;
    }
    #pragma unroll
    for (int q = 0; q < 4; ++q) {
        int ch  = tid + q * 256;
        int row = ch >> 3;
        int cb  = (ch & 7) * 16;
        dstB[q] = (uint32_t)A_STAGE_BYTES + swz((uint32_t)(row * 128 + cb));
        srcB[q] = (const char*)(gB + (size_t)row * DIN) + cb;
    }

    // ---- prologue: fill STAGES-1 stages ----
    int li = 0;
    #pragma unroll
    for (int s = 0; s < STAGES - 1; ++s) {
        uint32_t st = sb + s * STAGE_BYTES;
        #pragma unroll
        for (int q = 0; q < 2; ++q)
            CP_ASYNC_16(st + dstA[q], srcA[q] + li * (BK * 2));
        #pragma unroll
        for (int q = 0; q < 4; ++q)
            CP_ASYNC_16(st + dstB[q], srcB[q] + li * (BK * 2));
        CP_ASYNC_COMMIT();
        ++li;
    }

    // ---- ldmatrix per-lane address components ----
    const int rA = wm * 32 + (lane & 7) + ((lane >> 3) & 1) * 8;
    const uint32_t cA0 = ((lane >> 4) & 1) * 16;
    const uint32_t xrA = (uint32_t)((rA & 7) << 4);
    const int rB = wn * 32 + (lane & 7) + ((lane >> 4) & 1) * 8;
    const uint32_t cB0 = ((lane >> 3) & 1) * 16;
    const uint32_t xrB = (uint32_t)((rB & 7) << 4);

    float acc[2][4][4];
    #pragma unroll
    for (int i = 0; i < 2; ++i)
        #pragma unroll
        for (int j = 0; j < 4; ++j)
            #pragma unroll
            for (int r = 0; r < 4; ++r) acc[i][j][r] = 0.0f;

    // double-buffered fragments
    uint32_t afr[2][2][4];
    uint32_t bfr[2][2][4];

    // ---- main loop ----
    #pragma unroll 1
    for (int it = 0; it < NIT; ++it) {
        const int cur = it & (STAGES - 1);
        // issue load for stage (it+3)%4 (its previous contents were consumed
        // at iter it-1; the trailing __syncthreads of it-1 guards the reuse)
        if (li < NIT) {
            const int nx = (it + STAGES - 1) & (STAGES - 1);
            uint32_t st = sb + nx * STAGE_BYTES;
            #pragma unroll
            for (int q = 0; q < 2; ++q)
                CP_ASYNC_16(st + dstA[q], srcA[q] + li * (BK * 2));
            #pragma unroll
            for (int q = 0; q < 4; ++q)
                CP_ASYNC_16(st + dstB[q], srcB[q] + li * (BK * 2));
            ++li;
        }
        CP_ASYNC_COMMIT();
        CP_ASYNC_WAIT_3();   // oldest group (stage cur) complete
        __syncthreads();

        const uint32_t stA = sb + cur * STAGE_BYTES;
        const uint32_t stB = stA + A_STAGE_BYTES;

        // preload k-step 0 fragments
        #pragma unroll
        for (int i = 0; i < 2; ++i)
            LDSM_X4(afr[0][i], stA + (uint32_t)((rA + i * 16) * 128) + (cA0 ^ xrA));
        #pragma unroll
        for (int jj = 0; jj < 2; ++jj)
            LDSM_X4(bfr[0][jj], stB + (uint32_t)((rB + jj * 16) * 128) + (cB0 ^ xrB));

        // k-steps: prefetch s+1 fragments, then issue MMAs for s
        #pragma unroll
        for (int s = 0; s < 4; ++s) {
            const int cb = s & 1, nb = cb ^ 1;
            if (s < 3) {
                #pragma unroll
                for (int i = 0; i < 2; ++i)
                    LDSM_X4(afr[nb][i], stA + (uint32_t)((rA + i * 16) * 128)
                                            + ((cA0 + (s + 1) * 32) ^ xrA));
                #pragma unroll
                for (int jj = 0; jj < 2; ++jj)
                    LDSM_X4(bfr[nb][jj], stB + (uint32_t)((rB + jj * 16) * 128)
                                             + ((cB0 + (s + 1) * 32) ^ xrB));
            }
            #pragma unroll
            for (int i = 0; i < 2; ++i)
                #pragma unroll
                for (int j = 0; j < 4; ++j)
                    mma16816(acc[i][j], afr[cb][i], bfr[cb][j >> 1] + (j & 1) * 2);
        }
        __syncthreads();
    }

    // ---- epilogue: osc from amax globals (deterministic), scale + bias ----
    const float ax = __uint_as_float(g_amax_x_bits);
    const float aw = __uint_as_float(g_amax_w_bits);
    const float osc = (ax / QDIV) * (fmaxf(ax, aw) / QDIV);
    const int m0 = mt * BM + wm * 32 + (lane >> 2);
    const int n0 = nt * BN + wn * 32 + (lane & 3) * 2;
    #pragma unroll
    for (int i = 0; i < 2; ++i) {
        #pragma unroll
        for (int j = 0; j < 4; ++j) {
            const int m = m0 + i * 16;
            const int n = n0 + j * 8;
            const float b0 = __ldg(&bias[n]);
            const float b1 = __ldg(&bias[n + 1]);
            float2 v0, v1;
            v0.x = fmaf(acc[i][j][0], osc, b0);
            v0.y = fmaf(acc[i][j][1], osc, b1);
            v1.x = fmaf(acc[i][j][2], osc, b0);
            v1.y = fmaf(acc[i][j][3], osc, b1);
            *(float2*)&out[(size_t)m * DOUT + n]       = v0;
            *(float2*)&out[(size_t)(m + 8) * DOUT + n] = v1;
        }
    }
}

// ============================================================================
// kernel_launch: 4 launches (init, amax, quant, gemm)
// ============================================================================
extern "C" void kernel_launch(void* const* d_in, const int* in_sizes, int n_in,
                              void* d_out, int out_size) {
    const float* x    = (const float*)d_in[0];   // [4,2048,2048]
    const float* w    = (const float*)d_in[1];   // [2048,2048]
    const float* bias = (const float*)d_in[2];   // [2048]
    float* out = (float*)d_out;

    static int smem_set = 0;
    if (!smem_set) {
        cudaFuncSetAttribute(gemm_kernel,
                             cudaFuncAttributeMaxDynamicSharedMemorySize,
                             GEMM_SMEM_BYTES);
        smem_set = 1;
    }

    init_kernel<<<1, 1>>>();
    amax_kernel<<<1536, 256>>>((const float4*)x, (const float4*)w);
    quant_kernel<<<5120, 256>>>((const float4*)x, (const float4*)w);

    dim3 grid(DOUT / BN, M_TOTAL / BM);  // (16, 128) = 2048 CTAs
    gemm_kernel<<<grid, 256, GEMM_SMEM_BYTES>>>(out, bias);
}

// round 8
// speedup vs baseline: 1.1402x; 1.1402x over previous
#include <cuda_runtime.h>
#include <cuda_fp16.h>
#include <cstdint>

// ============================================================================
// Problem constants
// ============================================================================
#define M_TOTAL 8192   // B*S = 4*2048
#define DIN     2048
#define DOUT    2048
#define QDIV    358.4f // 448 * 0.8

// GEMM tiling (f16 carrier): 128x128 CTA tile, BK=64, 3 stages, 256 threads,
// 2 CTAs per SM (RF-bound optimum: 2 x 256 x 128 regs = full RF).
#define BM 128
#define BN 128
#define BK 64
#define STAGES 3
#define NIT (DIN / BK)   // 32

#define AMAX_XBLK 1024
#define AMAX_WBLK 512
#define QUANT_XBLK 4096
#define QUANT_WBLK 1024

// ============================================================================
// Device-global scratch (allocation-free requirement)
// ============================================================================
__device__ float g_px[AMAX_XBLK];   // per-block |x| maxes (plain stores)
__device__ float g_pw[AMAX_WBLK];   // per-block |w| maxes
__device__ float g_osc;             // sx*sw, published by quant block 0
// fp8-rounded values stored as f16 (exact: e4m3 subset of f16)
__device__ __align__(128) __half g_qx[(size_t)M_TOTAL * DIN];   // 32 MB
__device__ __align__(128) __half g_qw[(size_t)DOUT * DIN];      //  8 MB

// ============================================================================
// Helpers
// ============================================================================
__device__ __forceinline__ uint32_t smem_to_u32(const void* p) {
    uint32_t a;
    asm("{ .reg .u64 t; cvta.to.shared.u64 t, %1; cvt.u32.u64 %0, t; }"
        : "=r"(a) : "l"(p));
    return a;
}

// fp32x2 -> packed e4m3x2 (RN, satfinite). low byte = lo, high byte = hi.
__device__ __forceinline__ uint16_t cvt_e4m3x2(float hi, float lo) {
    uint16_t r;
    asm("cvt.rn.satfinite.e4m3x2.f32 %0, %1, %2;" : "=h"(r) : "f"(hi), "f"(lo));
    return r;
}

// packed e4m3x2 -> f16x2 (exact)
__device__ __forceinline__ uint32_t cvt_f16x2_from_e4m3x2(uint16_t e) {
    uint32_t r;
    asm("cvt.rn.f16x2.e4m3x2 %0, %1;" : "=r"(r) : "h"(e));
    return r;
}

#define CP_ASYNC_16(dst, src) \
    asm volatile("cp.async.cg.shared.global [%0], [%1], 16;" \
                 :: "r"(dst), "l"(src))
#define CP_ASYNC_COMMIT() asm volatile("cp.async.commit_group;")
#define CP_ASYNC_WAIT_1() asm volatile("cp.async.wait_group 1;")

#define LDSM_X4(r, addr) \
    asm volatile("ldmatrix.sync.aligned.m8n8.x4.shared.b16 {%0,%1,%2,%3}, [%4];" \
        : "=r"((r)[0]), "=r"((r)[1]), "=r"((r)[2]), "=r"((r)[3]) : "r"(addr))

__device__ __forceinline__ void mma16816(float* d, const uint32_t* a,
                                         const uint32_t* b) {
    asm volatile(
        "mma.sync.aligned.m16n8k16.row.col.f32.f16.f16.f32 "
        "{%0,%1,%2,%3}, {%4,%5,%6,%7}, {%8,%9}, {%0,%1,%2,%3};"
        : "+f"(d[0]), "+f"(d[1]), "+f"(d[2]), "+f"(d[3])
        : "r"(a[0]), "r"(a[1]), "r"(a[2]), "r"(a[3]), "r"(b[0]), "r"(b[1]));
}

// SW128 swizzle for 128-byte rows (byte offsets)
__device__ __forceinline__ uint32_t swz(uint32_t off) {
    return off ^ ((off >> 3) & 0x70);
}

// div via reciprocal + one FMA residual refinement (== IEEE div for all but
// ~2^-40 of inputs; 3-mantissa-bit e4m3 RNE absorbs the rest)
__device__ __forceinline__ float div_cr(float x, float s, float inv) {
    float y = x * inv;
    float e = fmaf(-s, y, x);
    return fmaf(e, inv, y);
}

// block-level max reduction (256 threads), result valid in thread 0
__device__ __forceinline__ float block_max_256(float m, float* sred) {
    #pragma unroll
    for (int o = 16; o; o >>= 1)
        m = fmaxf(m, __shfl_xor_sync(0xFFFFFFFFu, m, o));
    if ((threadIdx.x & 31) == 0) sred[threadIdx.x >> 5] = m;
    __syncthreads();
    if (threadIdx.x < 8) {
        m = sred[threadIdx.x];
        #pragma unroll
        for (int o = 4; o; o >>= 1)
            m = fmaxf(m, __shfl_xor_sync(0xFFu, m, o));
    }
    return m;
}

// ============================================================================
// Kernel 1: fused amax over x (blocks [0,1024)) and w (blocks [1024,1536)).
// Each block writes its block-max via PLAIN STORE to a partial array
// (no init needed; overwritten deterministically every call).
// ============================================================================
__global__ void amax_kernel(const float4* __restrict__ x,
                            const float4* __restrict__ w) {
    __shared__ float sred[8];
    const bool is_w = blockIdx.x >= AMAX_XBLK;
    const float4* p = is_w ? w : x;
    const int n4 = is_w ? (DOUT * DIN / 4) : (M_TOTAL * DIN / 4);
    const int nblk = is_w ? AMAX_WBLK : AMAX_XBLK;
    const int b0 = is_w ? AMAX_XBLK : 0;
    float m = 0.0f;
    for (int i = (blockIdx.x - b0) * blockDim.x + threadIdx.x; i < n4;
         i += nblk * blockDim.x) {
        float4 v = p[i];
        m = fmaxf(m, fmaxf(fmaxf(fabsf(v.x), fabsf(v.y)),
                           fmaxf(fabsf(v.z), fabsf(v.w))));
    }
    m = block_max_256(m, sred);
    if (threadIdx.x == 0) {
        if (is_w) g_pw[blockIdx.x - b0] = m;
        else      g_px[blockIdx.x] = m;
    }
}

// ============================================================================
// Kernel 2: fused quantize x (blocks [0,4096)) and w (blocks [4096,5120)).
// Every block first reduces the partial-max arrays (cheap: 6 loads/thread),
// computes scales inline, quantizes its slice. Block 0 publishes g_osc.
// Output: e4m3-rounded value stored exactly as f16.
// ============================================================================
__global__ void quant_kernel(const float4* __restrict__ x,
                             const float4* __restrict__ w) {
    __shared__ float sred[8];
    __shared__ float s_ax, s_aw;
    // reduce partials: ax over g_px[1024], aw over g_pw[512]
    {
        float mx = 0.0f, mw = 0.0f;
        #pragma unroll
        for (int q = 0; q < 4; ++q)
            mx = fmaxf(mx, g_px[threadIdx.x + q * 256]);
        #pragma unroll
        for (int q = 0; q < 2; ++q)
            mw = fmaxf(mw, g_pw[threadIdx.x + q * 256]);
        float rx = block_max_256(mx, sred);
        if (threadIdx.x == 0) s_ax = rx;
        __syncthreads();
        float rw = block_max_256(mw, sred);
        if (threadIdx.x == 0) s_aw = rw;
        __syncthreads();
    }
    const float ax = s_ax, aw = s_aw;
    if (blockIdx.x == 0 && threadIdx.x == 0)
        g_osc = (ax / QDIV) * (fmaxf(ax, aw) / QDIV);

    const bool is_w = blockIdx.x >= QUANT_XBLK;
    const float s   = is_w ? (fmaxf(ax, aw) / QDIV) : (ax / QDIV);
    const float inv = 1.0f / s;
    const float4* p = is_w ? w : x;
    uint2* q = (uint2*)(is_w ? (void*)g_qw : (void*)g_qx);
    const int n4 = is_w ? (DOUT * DIN / 4) : (M_TOTAL * DIN / 4);
    const int nblk = is_w ? QUANT_WBLK : QUANT_XBLK;
    const int b0 = is_w ? QUANT_XBLK : 0;
    for (int i = (blockIdx.x - b0) * blockDim.x + threadIdx.x; i < n4;
         i += nblk * blockDim.x) {
        float4 v = p[i];
        float y0 = div_cr(v.x, s, inv);
        float y1 = div_cr(v.y, s, inv);
        float y2 = div_cr(v.z, s, inv);
        float y3 = div_cr(v.w, s, inv);
        uint2 o;
        o.x = cvt_f16x2_from_e4m3x2(cvt_e4m3x2(y1, y0));
        o.y = cvt_f16x2_from_e4m3x2(cvt_e4m3x2(y3, y2));
        q[i] = o;
    }
}

// ============================================================================
// Kernel 3: f16 HMMA GEMM. out[m,n] = (sum_k qx[m,k]*qw[n,k])*osc + bias[n]
// 128x128x64 CTA tile, 3-stage cp.async, SW128 swizzle, 2 CTAs/SM,
// 8 warps 2(M)x4(N), warp tile 64x32, m16n8k16,
// intra-stage fragment double buffering; k0 preload hoisted to loop top.
// ============================================================================
#define STAGE_BYTES 32768                 // A 16KB + B 16KB
#define GEMM_SMEM_BYTES (STAGES * STAGE_BYTES)   // 98304

__global__ __launch_bounds__(256, 2) void gemm_kernel(
    float* __restrict__ out, const float* __restrict__ bias)
{
    extern __shared__ char smem[];
    const uint32_t sb = smem_to_u32(smem);
    const int tid  = threadIdx.x;
    const int lane = tid & 31;
    const int warp = tid >> 5;
    const int wm = warp >> 2;       // 0..1
    const int wn = warp & 3;        // 0..3
    const int nt = blockIdx.x;      // 0..15
    const int mt = blockIdx.y;      // 0..63

    const __half* gA = g_qx + (size_t)mt * BM * DIN;
    const __half* gB = g_qw + (size_t)nt * BN * DIN;

    // ---- per-thread cp.async chunk map: 4 chunks A + 4 chunks B per stage ----
    uint32_t dstA[4], dstB[4];
    const char* srcA[4];
    const char* srcB[4];
    #pragma unroll
    for (int q = 0; q < 4; ++q) {
        int ch  = tid + q * 256;
        int row = ch >> 3;
        int cb  = (ch & 7) * 16;
        uint32_t sw = swz((uint32_t)(row * 128 + cb));
        dstA[q] = sw;
        dstB[q] = 16384u + sw;
        srcA[q] = (const char*)(gA + (size_t)row * DIN) + cb;
        srcB[q] = (const char*)(gB + (size_t)row * DIN) + cb;
    }

    // ---- prologue: fill STAGES-1 stages ----
    int li = 0;
    #pragma unroll
    for (int s = 0; s < STAGES - 1; ++s) {
        uint32_t st = sb + s * STAGE_BYTES;
        #pragma unroll
        for (int q = 0; q < 4; ++q) {
            CP_ASYNC_16(st + dstA[q], srcA[q] + li * (BK * 2));
            CP_ASYNC_16(st + dstB[q], srcB[q] + li * (BK * 2));
        }
        CP_ASYNC_COMMIT();
        ++li;
    }
    CP_ASYNC_WAIT_1();
    __syncthreads();

    // ---- ldmatrix per-lane address components ----
    const int rA = wm * 64 + (lane & 7) + ((lane >> 3) & 1) * 8;
    const uint32_t cA0 = ((lane >> 4) & 1) * 16;
    const uint32_t xrA = (uint32_t)((rA & 7) << 4);
    const int rB = wn * 32 + (lane & 7) + ((lane >> 4) & 1) * 8;
    const uint32_t cB0 = ((lane >> 3) & 1) * 16;
    const uint32_t xrB = (uint32_t)((rB & 7) << 4);

    float acc[4][4][4];
    #pragma unroll
    for (int i = 0; i < 4; ++i)
        #pragma unroll
        for (int j = 0; j < 4; ++j)
            #pragma unroll
            for (int r = 0; r < 4; ++r) acc[i][j][r] = 0.0f;

    // double-buffered fragments
    uint32_t afr[2][4][4];
    uint32_t bfr[2][2][4];

    // ---- main loop ----
    #pragma unroll 1
    for (int it = 0; it < NIT; ++it) {
        const int cur = it % STAGES;
        const uint32_t stA = sb + cur * STAGE_BYTES;
        const uint32_t stB = stA + 16384;

        // k0 fragment preload FIRST (stage cur is complete and synced);
        // gets LDSM latency covered by the cp.async issue below.
        #pragma unroll
        for (int i = 0; i < 4; ++i)
            LDSM_X4(afr[0][i], stA + (uint32_t)((rA + i * 16) * 128) + (cA0 ^ xrA));
        #pragma unroll
        for (int jj = 0; jj < 2; ++jj)
            LDSM_X4(bfr[0][jj], stB + (uint32_t)((rB + jj * 16) * 128) + (cB0 ^ xrB));

        // issue loads for stage (it+2)%3 (consumed at it-1; end-of-iter sync guards)
        if (li < NIT) {
            const int nx = (it + STAGES - 1) % STAGES;
            uint32_t st = sb + nx * STAGE_BYTES;
            #pragma unroll
            for (int q = 0; q < 4; ++q) {
                CP_ASYNC_16(st + dstA[q], srcA[q] + li * (BK * 2));
                CP_ASYNC_16(st + dstB[q], srcB[q] + li * (BK * 2));
            }
            ++li;
        }
        CP_ASYNC_COMMIT();

        // k-steps: prefetch s+1 fragments, then issue MMAs for s
        #pragma unroll
        for (int s = 0; s < 4; ++s) {
            const int cb = s & 1, nb = cb ^ 1;
            if (s < 3) {
                #pragma unroll
                for (int i = 0; i < 4; ++i)
                    LDSM_X4(afr[nb][i], stA + (uint32_t)((rA + i * 16) * 128)
                                            + ((cA0 + (s + 1) * 32) ^ xrA));
                #pragma unroll
                for (int jj = 0; jj < 2; ++jj)
                    LDSM_X4(bfr[nb][jj], stB + (uint32_t)((rB + jj * 16) * 128)
                                             + ((cB0 + (s + 1) * 32) ^ xrB));
            }
            #pragma unroll
            for (int i = 0; i < 4; ++i)
                #pragma unroll
                for (int j = 0; j < 4; ++j)
                    mma16816(acc[i][j], afr[cb][i], bfr[cb][j >> 1] + (j & 1) * 2);
        }

        CP_ASYNC_WAIT_1();
        __syncthreads();
    }

    // ---- epilogue: scale + bias ----
    const float osc = g_osc;
    const int m0 = mt * BM + wm * 64 + (lane >> 2);
    const int n0 = nt * BN + wn * 32 + (lane & 3) * 2;
    #pragma unroll
    for (int i = 0; i < 4; ++i) {
        #pragma unroll
        for (int j = 0; j < 4; ++j) {
            const int m = m0 + i * 16;
            const int n = n0 + j * 8;
            const float b0 = __ldg(&bias[n]);
            const float b1 = __ldg(&bias[n + 1]);
            float2 v0, v1;
            v0.x = fmaf(acc[i][j][0], osc, b0);
            v0.y = fmaf(acc[i][j][1], osc, b1);
            v1.x = fmaf(acc[i][j][2], osc, b0);
            v1.y = fmaf(acc[i][j][3], osc, b1);
            *(float2*)&out[(size_t)m * DOUT + n]       = v0;
            *(float2*)&out[(size_t)(m + 8) * DOUT + n] = v1;
        }
    }
}

// ============================================================================
// kernel_launch: 3 launches (amax, quant, gemm)
// ============================================================================
extern "C" void kernel_launch(void* const* d_in, const int* in_sizes, int n_in,
                              void* d_out, int out_size) {
    const float* x    = (const float*)d_in[0];   // [4,2048,2048]
    const float* w    = (const float*)d_in[1];   // [2048,2048]
    const float* bias = (const float*)d_in[2];   // [2048]
    float* out = (float*)d_out;

    static int smem_set = 0;
    if (!smem_set) {
        cudaFuncSetAttribute(gemm_kernel,
                             cudaFuncAttributeMaxDynamicSharedMemorySize,
                             GEMM_SMEM_BYTES);
        smem_set = 1;
    }

    amax_kernel<<<AMAX_XBLK + AMAX_WBLK, 256>>>((const float4*)x,
                                                (const float4*)w);
    quant_kernel<<<QUANT_XBLK + QUANT_WBLK, 256>>>((const float4*)x,
                                                   (const float4*)w);

    dim3 grid(DOUT / BN, M_TOTAL / BM);  // (16, 64) = 1024 CTAs
    gemm_kernel<<<grid, 256, GEMM_SMEM_BYTES>>>(out, bias);
}